// round 9
// baseline (speedup 1.0000x reference)
#include <cuda_runtime.h>
#include <cstdint>

// Model_35347580846430: reflect-pad depthwise moving average, W=25, PAD=12
// x: [B=64, T=4096, N=128] f32, out same shape.
// out[b,t,n] = mean_{k=-12..12} x[b, reflect(t+k), n]
//
// R9: combine R7's 2-blocks/SM overlap with R8's intra-block double buffer.
// T_TILE=64 -> 45KB buffers, 2 buffers = 90KB/block, 2 blocks/SM (176KB).
// Each block pipelines an 8-tile strip (prefetch i+1, wait_group 1, compute i).
// R8 failed because 152KB smem forced 1 block/SM and lost inter-block overlap;
// this gets both. Halo re-reads dedup in L2 (R7: 216MB measured DRAM traffic).

#define B_DIM   64
#define T_DIM   4096
#define N_DIM   128
#define PAD     12
#define WIN     25
#define T_TILE  64
#define HALO    (2 * PAD)            // 24
#define ROWS    (T_TILE + HALO)      // 88 smem rows per buffer
#define N4      (N_DIM / 4)          // 32 float4 per row
#define NTHR    256
#define K_TILES 8
#define T_STRIP (T_TILE * K_TILES)   // 512
#define BUF_ELEMS (ROWS * N4)
#define SMEM_BYTES (2 * ROWS * N_DIM * 4)   // 90112 (88 KB)

__device__ __forceinline__ int reflect_idx(int t) {
    // np.pad 'reflect': x[-1] -> x[1], x[T] -> x[T-2]
    t = (t < 0) ? -t : t;
    t = (t >= T_DIM) ? (2 * (T_DIM - 1) - t) : t;
    return t;
}

__global__ __launch_bounds__(NTHR, 2)
void ma25_kernel(const float4* __restrict__ x, float4* __restrict__ out) {
    extern __shared__ float4 smem[];          // [2][ROWS][N4]

    const int tid  = threadIdx.x;
    const int lane = tid & 31;                // float4 column 0..31
    const int grp  = tid >> 5;                // 0..7
    const int b    = blockIdx.y;
    const int s0   = blockIdx.x * T_STRIP;    // strip start (t)

    const float4* __restrict__ xb = x + (size_t)b * T_DIM * N4 + lane;
    const float inv = 1.0f / (float)WIN;

    // ---- async tile loader: 88 rows, 8 rows/iter, 11 cp.asyncs per thread
    auto load_tile = [&](int tile, int buf) {
        const int t0 = s0 + tile * T_TILE;
        float4* dstb = smem + buf * BUF_ELEMS;
        #pragma unroll
        for (int it = 0; it < ROWS / 8; it++) {
            const int r = it * 8 + grp;
            const int t = reflect_idx(t0 - PAD + r);
            const float4* src = xb + (size_t)t * N4;
            uint32_t dst = (uint32_t)__cvta_generic_to_shared(&dstb[r * N4 + lane]);
            asm volatile("cp.async.cg.shared.global [%0], [%1], 16;"
                         :: "r"(dst), "l"(src) : "memory");
        }
        asm volatile("cp.async.commit_group;" ::: "memory");
    };

    load_tile(0, 0);

    #pragma unroll
    for (int i = 0; i < K_TILES; i++) {
        // Prefetch next tile before consuming current one.
        if (i + 1 < K_TILES) {
            load_tile(i + 1, (i + 1) & 1);
            asm volatile("cp.async.wait_group 1;" ::: "memory");
        } else {
            asm volatile("cp.async.wait_group 0;" ::: "memory");
        }
        __syncthreads();

        // ---- compute tile i from buffer i&1: group owns 8 rows
        const float4* bs = smem + (i & 1) * BUF_ELEMS;
        const int r0 = grp * 8;
        float4* __restrict__ ob =
            out + (size_t)(b * T_DIM + s0 + i * T_TILE) * N4 + lane;

        float sx = 0.f, sy = 0.f, sz = 0.f, sw = 0.f;
        #pragma unroll
        for (int j = 0; j < HALO; j++) {
            float4 v = bs[(r0 + j) * N4 + lane];
            sx += v.x; sy += v.y; sz += v.z; sw += v.w;
        }

        #pragma unroll
        for (int k = 0; k < 8; k++) {
            const int r = r0 + k;
            float4 vin = bs[(r + HALO) * N4 + lane];
            float wx = sx + vin.x, wy = sy + vin.y, wz = sz + vin.z, ww = sw + vin.w;

            float4 o; o.x = wx * inv; o.y = wy * inv; o.z = wz * inv; o.w = ww * inv;
            ob[(size_t)r * N4] = o;

            float4 vout = bs[r * N4 + lane];
            sx = wx - vout.x; sy = wy - vout.y; sz = wz - vout.z; sw = ww - vout.w;
        }

        // Buffer i&1 is overwritten by load_tile(i+2) next iteration:
        // all threads must finish reading it first.
        __syncthreads();
    }
}

extern "C" void kernel_launch(void* const* d_in, const int* in_sizes, int n_in,
                              void* d_out, int out_size) {
    const float4* x = (const float4*)d_in[0];
    float4* out = (float4*)d_out;

    cudaFuncSetAttribute(ma25_kernel,
                         cudaFuncAttributeMaxDynamicSharedMemorySize, SMEM_BYTES);

    dim3 block(NTHR);
    dim3 grid(T_DIM / T_STRIP, B_DIM);             // (8, 64) = 512 blocks
    ma25_kernel<<<grid, block, SMEM_BYTES>>>(x, out);
}

// round 10
// speedup vs baseline: 1.0801x; 1.0801x over previous
#include <cuda_runtime.h>
#include <cstdint>

// Model_35347580846430: reflect-pad depthwise moving average, W=25, PAD=12
// x: [B=64, T=4096, N=128] f32, out same shape.
// out[b,t,n] = mean_{k=-12..12} x[b, reflect(t+k), n]
//
// R10: R7 base (single-buffer cp.async tile, 2 blocks/SM natural overlap —
// it beat both explicit pipelines) + register-kept outgoing rows. R7/R8/R9
// all sat at ~5TB/s because the compute phase is smem-crossbar-bound
// (305KB smem traffic per 76KB tile > the tile's DRAM fill time). The
// outgoing row at step k is halo row r0+k, already read during the halo sum:
// keep the first 16 halo rows in registers -> steady-state 1 LDS/output
// instead of 2. Tile smem traffic 305 -> 240KB.

#define B_DIM  64
#define T_DIM  4096
#define N_DIM  128
#define PAD    12
#define WIN    25
#define T_TILE 128
#define HALO   (2 * PAD)            // 24
#define ROWS   (T_TILE + HALO)      // 152 smem rows
#define N4     (N_DIM / 4)          // 32 float4 per row
#define NTHR   256
#define KROWS  16                   // output rows per thread
#define SMEM_BYTES (ROWS * N_DIM * 4)   // 77824

__device__ __forceinline__ int reflect_idx(int t) {
    // np.pad 'reflect': x[-1] -> x[1], x[T] -> x[T-2]
    t = (t < 0) ? -t : t;
    t = (t >= T_DIM) ? (2 * (T_DIM - 1) - t) : t;
    return t;
}

__global__ __launch_bounds__(NTHR, 2)
void ma25_kernel(const float4* __restrict__ x, float4* __restrict__ out) {
    extern __shared__ float4 smem[];          // [ROWS][N4]

    const int tid  = threadIdx.x;
    const int lane = tid & 31;                // float4 column 0..31
    const int grp  = tid >> 5;                // 0..7
    const int b    = blockIdx.y;
    const int t0   = blockIdx.x * T_TILE;

    const float4* __restrict__ xb = x + (size_t)b * T_DIM * N4 + lane;

    // ---- Load phase: 152 rows, 8 rows per iteration, 19 cp.asyncs/thread.
    #pragma unroll
    for (int it = 0; it < ROWS / 8; it++) {
        const int r = it * 8 + grp;
        const int t = reflect_idx(t0 - PAD + r);
        const float4* src = xb + (size_t)t * N4;
        uint32_t dst = (uint32_t)__cvta_generic_to_shared(&smem[r * N4 + lane]);
        asm volatile("cp.async.cg.shared.global [%0], [%1], 16;"
                     :: "r"(dst), "l"(src) : "memory");
    }
    asm volatile("cp.async.commit_group;" ::: "memory");
    asm volatile("cp.async.wait_group 0;" ::: "memory");
    __syncthreads();

    // ---- Compute phase: thread owns column `lane`, output rows [r0, r0+16).
    // Output row i (global t0+i) uses smem rows i .. i+24.
    const int r0 = grp * KROWS;
    const float inv = 1.0f / (float)WIN;

    float4* __restrict__ ob = out + (size_t)(b * T_DIM + t0) * N4 + lane;

    // Halo sum over rows r0 .. r0+23; keep the first KROWS rows in registers
    // (they are the outgoing values for steps 0..KROWS-1).
    float4 keep[KROWS];
    float sx = 0.f, sy = 0.f, sz = 0.f, sw = 0.f;
    #pragma unroll
    for (int j = 0; j < HALO; j++) {
        float4 v = smem[(r0 + j) * N4 + lane];
        if (j < KROWS) keep[j] = v;
        sx += v.x; sy += v.y; sz += v.z; sw += v.w;
    }

    #pragma unroll
    for (int k = 0; k < KROWS; k++) {
        const int r = r0 + k;
        float4 vin = smem[(r + HALO) * N4 + lane];   // incoming row i+24
        float wx = sx + vin.x, wy = sy + vin.y, wz = sz + vin.z, ww = sw + vin.w;

        float4 o; o.x = wx * inv; o.y = wy * inv; o.z = wz * inv; o.w = ww * inv;
        ob[(size_t)r * N4] = o;

        // outgoing row i comes from registers, not smem
        sx = wx - keep[k].x; sy = wy - keep[k].y;
        sz = wz - keep[k].z; sw = ww - keep[k].w;
    }
}

extern "C" void kernel_launch(void* const* d_in, const int* in_sizes, int n_in,
                              void* d_out, int out_size) {
    const float4* x = (const float4*)d_in[0];
    float4* out = (float4*)d_out;

    cudaFuncSetAttribute(ma25_kernel,
                         cudaFuncAttributeMaxDynamicSharedMemorySize, SMEM_BYTES);

    dim3 block(NTHR);
    dim3 grid(T_DIM / T_TILE, B_DIM);              // (32, 64) = 2048 blocks
    ma25_kernel<<<grid, block, SMEM_BYTES>>>(x, out);
}

// round 11
// speedup vs baseline: 1.0809x; 1.0007x over previous
#include <cuda_runtime.h>
#include <cstdint>

// Model_35347580846430: reflect-pad depthwise moving average, W=25, PAD=12
// x: [B=64, T=4096, N=128] f32, out same shape.
// out[b,t,n] = mean_{k=-12..12} x[b, reflect(t+k), n]
//
// R11: phase-diversity fix. R7-R10 all capped at ~64% DRAM duty because the
// 2 resident blocks/SM phase-lock (load together, compute together -> DRAM
// idles every compute phase). Split each tile's N across 2 blocks:
// 128-thread blocks, 38KB buffer -> 6 blocks/SM. With 6 independent
// load/compute cycles per SM, some block is always loading.
// Halo reads duplicate across N-halves but dedup in L2 (R7: DRAM traffic
// already below compulsory floor thanks to L2-resident input).

#define B_DIM  64
#define T_DIM  4096
#define N_DIM  128
#define PAD    12
#define WIN    25
#define T_TILE 128
#define HALO   (2 * PAD)            // 24
#define ROWS   (T_TILE + HALO)      // 152 smem rows
#define N4     (N_DIM / 4)          // 32 float4 per full row
#define N4H    16                   // float4 per half row (this block's share)
#define NTHR   128
#define KROWS  16                   // output rows per thread
#define SMEM_BYTES (ROWS * N4H * 16)    // 38912

__device__ __forceinline__ int reflect_idx(int t) {
    // np.pad 'reflect': x[-1] -> x[1], x[T] -> x[T-2]
    t = (t < 0) ? -t : t;
    t = (t >= T_DIM) ? (2 * (T_DIM - 1) - t) : t;
    return t;
}

__global__ __launch_bounds__(NTHR, 6)
void ma25_kernel(const float4* __restrict__ x, float4* __restrict__ out) {
    extern __shared__ float4 smem[];          // [ROWS][N4H]

    const int tid  = threadIdx.x;
    const int lane = tid & 15;                // float4 column 0..15 within half
    const int grp  = tid >> 4;                // 0..7 row groups
    const int b    = blockIdx.y;
    const int t0   = blockIdx.x * T_TILE;
    const int n0   = blockIdx.z * N4H;        // which N-half

    const float4* __restrict__ xb = x + (size_t)b * T_DIM * N4 + n0 + lane;

    // ---- Load phase: 152 rows, 8 rows/iter, 19 cp.asyncs per thread.
    #pragma unroll
    for (int it = 0; it < ROWS / 8; it++) {
        const int r = it * 8 + grp;
        const int t = reflect_idx(t0 - PAD + r);
        const float4* src = xb + (size_t)t * N4;
        uint32_t dst = (uint32_t)__cvta_generic_to_shared(&smem[r * N4H + lane]);
        asm volatile("cp.async.cg.shared.global [%0], [%1], 16;"
                     :: "r"(dst), "l"(src) : "memory");
    }
    asm volatile("cp.async.commit_group;" ::: "memory");
    asm volatile("cp.async.wait_group 0;" ::: "memory");
    __syncthreads();

    // ---- Compute phase: thread owns column `lane`, output rows [r0, r0+16).
    const int r0 = grp * KROWS;
    const float inv = 1.0f / (float)WIN;

    float4* __restrict__ ob = out + (size_t)(b * T_DIM + t0) * N4 + n0 + lane;

    float sx = 0.f, sy = 0.f, sz = 0.f, sw = 0.f;
    #pragma unroll
    for (int j = 0; j < HALO; j++) {
        float4 v = smem[(r0 + j) * N4H + lane];
        sx += v.x; sy += v.y; sz += v.z; sw += v.w;
    }

    #pragma unroll
    for (int k = 0; k < KROWS; k++) {
        const int r = r0 + k;
        float4 vin = smem[(r + HALO) * N4H + lane];   // incoming row r+24
        float wx = sx + vin.x, wy = sy + vin.y, wz = sz + vin.z, ww = sw + vin.w;

        float4 o; o.x = wx * inv; o.y = wy * inv; o.z = wz * inv; o.w = ww * inv;
        ob[(size_t)r * N4] = o;

        float4 vout = smem[r * N4H + lane];           // outgoing row r
        sx = wx - vout.x; sy = wy - vout.y;
        sz = wz - vout.z; sw = ww - vout.w;
    }
}

extern "C" void kernel_launch(void* const* d_in, const int* in_sizes, int n_in,
                              void* d_out, int out_size) {
    const float4* x = (const float4*)d_in[0];
    float4* out = (float4*)d_out;

    cudaFuncSetAttribute(ma25_kernel,
                         cudaFuncAttributeMaxDynamicSharedMemorySize, SMEM_BYTES);

    dim3 block(NTHR);
    dim3 grid(T_DIM / T_TILE, B_DIM, 2);           // (32, 64, 2) = 4096 blocks
    ma25_kernel<<<grid, block, SMEM_BYTES>>>(x, out);
}